// round 16
// baseline (speedup 1.0000x reference)
#include <cuda_runtime.h>
#include <cstdint>
#include <math.h>

// ---------------------------------------------------------------------------
// DeformableConv2d: B=8, C=112, H=W=64, O=112, K=3, G=14, stride=1, pad=1
// pg channels: 378 = 252 offsets (interleaved dy/dx per (g,k)) + 126 mask
// ---------------------------------------------------------------------------

#define BB 8
#define CC 112
#define HH 64
#define WW 64
#define OO 112
#define GG 14
#define K2 9
#define PGC 378            // 3*G*K2
#define HW 4096            // 64*64
#define CK 1008            // C*K2

// scratch (allocation-free rule: static __device__ arrays)
__device__ float g_pg[BB * PGC * HW];          // 47.25 MiB
__device__ float g_smp[BB * CC * K2 * HW];     // 126 MiB

// ---------------------------------------------------------------------------
// Kernel 1 (R9 winner + 3 CTA/SM): pg = conv3x3(x, pg_weight, pad=1) + pg_bias
// Block: 256 threads -> 64 oc x 128 px (2 output rows). c-chunks of 8.
// Thread map: og = t&15, pg = t>>4 (x broadcast, w conflict-free).
// Thread tile: 4 oc x 8 px.
// __launch_bounds__(256, 3): cap regs at ~85 -> 24 warps/SM to hide LDS
// latency and fill-barrier stalls (was 16 warps @ 125 regs).
// ---------------------------------------------------------------------------
__global__ __launch_bounds__(256, 3) void k1_pgconv(const float* __restrict__ x,
                                                    const float* __restrict__ pw,
                                                    const float* __restrict__ pb)
{
    const int ocTile = blockIdx.x;     // 0..5  (6*64 = 384 >= 378)
    const int rp     = blockIdx.y;     // 0..31 row pair
    const int b      = blockIdx.z;     // 0..7
    const int t      = threadIdx.x;
    const int oh0    = rp * 2;

    const int og   = t & 15;           // 16 oc groups * 4 oc
    const int pg   = t >> 4;           // 16 pixel groups
    const int r    = pg >> 3;          // 0/1 : which output row
    const int col0 = (pg & 7) * 8;     // 8 contiguous columns
    const int ocl0 = og * 4;
    const int oc0  = ocTile * 64;

    __shared__ __align__(16) float xs[4][8][68];
    __shared__ __align__(16) float ws[72 * 64];   // [ck][oc]

    // halo columns (iw=-1 at [0], iw=64 at [65]) always OOB -> zero once
    if (t < 64) {
        int rr = t >> 4, cl = (t >> 1) & 7, side = t & 1;
        xs[rr][cl][side * 65] = 0.f;
    }

    float acc[4][8];
#pragma unroll
    for (int j = 0; j < 4; ++j)
#pragma unroll
        for (int i = 0; i < 8; ++i) acc[j][i] = 0.f;

    for (int c0 = 0; c0 < CC; c0 += 8) {
        __syncthreads();
        // ---- input tile: 4 rows x 8 ch x 64 inner cols (2048 = 8*256)
        {
            int idx = t;
#pragma unroll
            for (int i = 0; i < 8; ++i, idx += 256) {
                int col = idx & 63;
                int cl  = (idx >> 6) & 7;
                int rr  = idx >> 9;
                int ih  = oh0 - 1 + rr;
                float v = 0.f;
                if ((unsigned)ih < 64u)
                    v = x[(((size_t)b * CC + c0 + cl) * HH + ih) * WW + col];
                xs[rr][cl][col + 1] = v;
            }
        }
        // ---- weight tile: 72 ck x 64 oc (4608 = 18*256), [ck][oc]
        {
            int idx = t;
#pragma unroll
            for (int i = 0; i < 18; ++i, idx += 256) {
                int ocl = idx & 63;
                int ck  = idx >> 6;
                int oc  = oc0 + ocl;
                float v = (oc < PGC) ? pw[(size_t)oc * CK + c0 * 9 + ck] : 0.f;
                ws[ck * 64 + ocl] = v;
            }
        }
        __syncthreads();

#pragma unroll
        for (int cl = 0; cl < 8; ++cl) {
#pragma unroll
            for (int ky = 0; ky < 3; ++ky) {
                const float* xrow = &xs[r + ky][cl][col0];
                const float4 xa = *(const float4*)(xrow);
                const float4 xb = *(const float4*)(xrow + 4);
                const float2 xc = *(const float2*)(xrow + 8);
                const float xv[10] = { xa.x, xa.y, xa.z, xa.w,
                                       xb.x, xb.y, xb.z, xb.w,
                                       xc.x, xc.y };
#pragma unroll
                for (int kx = 0; kx < 3; ++kx) {
                    const float4 wv =
                        *(const float4*)(&ws[(cl * 9 + ky * 3 + kx) * 64 + ocl0]);
#pragma unroll
                    for (int i = 0; i < 8; ++i) {
                        acc[0][i] = fmaf(wv.x, xv[i + kx], acc[0][i]);
                        acc[1][i] = fmaf(wv.y, xv[i + kx], acc[1][i]);
                        acc[2][i] = fmaf(wv.z, xv[i + kx], acc[2][i]);
                        acc[3][i] = fmaf(wv.w, xv[i + kx], acc[3][i]);
                    }
                }
            }
        }
    }

#pragma unroll
    for (int j = 0; j < 4; ++j) {
        int oc = oc0 + ocl0 + j;
        if (oc < PGC) {
            float bv = pb[oc];
            float* dst = &g_pg[(((size_t)b * PGC + oc) * HH + oh0 + r) * WW + col0];
            float4 v0 = make_float4(acc[j][0] + bv, acc[j][1] + bv,
                                    acc[j][2] + bv, acc[j][3] + bv);
            float4 v1 = make_float4(acc[j][4] + bv, acc[j][5] + bv,
                                    acc[j][6] + bv, acc[j][7] + bv);
            *(float4*)(dst)     = v0;
            *(float4*)(dst + 4) = v1;
        }
    }
}

// ---------------------------------------------------------------------------
// Kernel 2: bilinear sampling * sigmoid(mask)
// One thread per (b, g, k, pixel). dy = pg[g*18+2k], dx = pg[g*18+2k+1]
// (interleaved!), mask = sigmoid(pg[252 + g*9 + k]).
// Output layout: g_smp[b][c][k][p]
// ---------------------------------------------------------------------------
__global__ __launch_bounds__(256) void k2_sample(const float* __restrict__ x)
{
    int gid = blockIdx.x * 256 + threadIdx.x;
    const int TOT = BB * GG * K2 * HW;   // 4,128,768
    if (gid >= TOT) return;

    int p    = gid & (HW - 1);
    int rest = gid >> 12;
    int gk   = rest % (GG * K2);
    int b    = rest / (GG * K2);
    int g    = gk / 9;
    int k    = gk - g * 9;
    int oh   = p >> 6, ow = p & 63;

    const float* pgb = g_pg + (size_t)b * PGC * HW;
    float dy = pgb[(g * 18 + 2 * k) * HW + p];
    float dx = pgb[(g * 18 + 2 * k + 1) * HW + p];
    float m  = pgb[(252 + gk) * HW + p];
    float mask = 1.f / (1.f + expf(-m));

    float yy = (float)(oh - 1 + k / 3) + dy;
    float xx = (float)(ow - 1 + k % 3) + dx;
    float y0f = floorf(yy), x0f = floorf(xx);
    float wy1 = yy - y0f, wx1 = xx - x0f;
    float wy0 = 1.f - wy1, wx0 = 1.f - wx1;
    int y0 = (int)y0f, x0i = (int)x0f;
    int y1 = y0 + 1, x1 = x0i + 1;
    bool vy0 = (unsigned)y0 < 64u, vy1 = (unsigned)y1 < 64u;
    bool vx0 = (unsigned)x0i < 64u, vx1 = (unsigned)x1 < 64u;

    float w00 = (vy0 && vx0) ? wy0 * wx0 * mask : 0.f;
    float w01 = (vy0 && vx1) ? wy0 * wx1 * mask : 0.f;
    float w10 = (vy1 && vx0) ? wy1 * wx0 * mask : 0.f;
    float w11 = (vy1 && vx1) ? wy1 * wx1 * mask : 0.f;

    int yc0 = min(max(y0, 0), 63), yc1 = min(max(y1, 0), 63);
    int xc0 = min(max(x0i, 0), 63), xc1 = min(max(x1, 0), 63);
    int i00 = yc0 * 64 + xc0, i01 = yc0 * 64 + xc1;
    int i10 = yc1 * 64 + xc0, i11 = yc1 * 64 + xc1;

    const float* xb = x + ((size_t)b * CC + g * 8) * HW;
    float* out = g_smp + ((((size_t)b * CC + g * 8) * K2) + k) * HW + p;
#pragma unroll
    for (int c = 0; c < 8; ++c) {
        const float* xc = xb + (size_t)c * HW;
        float v = w00 * xc[i00] + w01 * xc[i01] + w10 * xc[i10] + w11 * xc[i11];
        out[(size_t)c * K2 * HW] = v;
    }
}

// ---------------------------------------------------------------------------
// Kernel 3: out[b,o,p] = bias[o] + sum_ck smp[b,ck,p] * W[o,ck]
// Block: 256 threads -> 112 O x 128 px. Thread tile: 7 oc x 8 px. K-chunk 16.
// ---------------------------------------------------------------------------
__global__ __launch_bounds__(256) void k3_gemm(const float* __restrict__ w2,
                                               const float* __restrict__ bias,
                                               float* __restrict__ out)
{
    const int pt = blockIdx.x;       // 0..31
    const int b  = blockIdx.y;       // 0..7
    const int t  = threadIdx.x;
    const int pxg = t & 15;          // 16 groups * 8 px
    const int ocg = t >> 4;          // 16 groups * 7 oc
    const int p0  = pt * 128;
    const int px0 = pxg * 8;

    __shared__ __align__(16) float ss[16 * 128];   // [ckl][px]
    __shared__ float ws2[16 * 113];                // [ckl][o] pad

    float acc[7][8];
#pragma unroll
    for (int j = 0; j < 7; ++j)
#pragma unroll
        for (int i = 0; i < 8; ++i) acc[j][i] = 0.f;

    const float* sb = g_smp + (size_t)b * CK * HW + p0;

    for (int ck0 = 0; ck0 < CK; ck0 += 16) {
        __syncthreads();
        {
            int idx = t;
#pragma unroll
            for (int i = 0; i < 8; ++i, idx += 256) {
                int pxl = idx & 127;
                int ckl = idx >> 7;
                ss[ckl * 128 + pxl] = sb[(size_t)(ck0 + ckl) * HW + pxl];
            }
        }
        {
            int idx = t;
#pragma unroll
            for (int i = 0; i < 7; ++i, idx += 256) {
                int ckl = idx & 15;
                int o   = idx >> 4;
                ws2[ckl * 113 + o] = w2[(size_t)o * CK + ck0 + ckl];
            }
        }
        __syncthreads();

#pragma unroll
        for (int ckl = 0; ckl < 16; ++ckl) {
            float4 sa = *(const float4*)(&ss[ckl * 128 + px0]);
            float4 sc = *(const float4*)(&ss[ckl * 128 + px0 + 4]);
            const float* wr = &ws2[ckl * 113 + ocg * 7];
#pragma unroll
            for (int j = 0; j < 7; ++j) {
                float wv = wr[j];
                acc[j][0] = fmaf(wv, sa.x, acc[j][0]);
                acc[j][1] = fmaf(wv, sa.y, acc[j][1]);
                acc[j][2] = fmaf(wv, sa.z, acc[j][2]);
                acc[j][3] = fmaf(wv, sa.w, acc[j][3]);
                acc[j][4] = fmaf(wv, sc.x, acc[j][4]);
                acc[j][5] = fmaf(wv, sc.y, acc[j][5]);
                acc[j][6] = fmaf(wv, sc.z, acc[j][6]);
                acc[j][7] = fmaf(wv, sc.w, acc[j][7]);
            }
        }
    }

#pragma unroll
    for (int j = 0; j < 7; ++j) {
        int o = ocg * 7 + j;
        float bv = bias[o];
        float* dst = &out[(((size_t)b * OO + o) * HW) + p0 + px0];
        float4 v0 = make_float4(acc[j][0] + bv, acc[j][1] + bv,
                                acc[j][2] + bv, acc[j][3] + bv);
        float4 v1 = make_float4(acc[j][4] + bv, acc[j][5] + bv,
                                acc[j][6] + bv, acc[j][7] + bv);
        *(float4*)(dst)     = v0;
        *(float4*)(dst + 4) = v1;
    }
}

// ---------------------------------------------------------------------------
extern "C" void kernel_launch(void* const* d_in, const int* in_sizes, int n_in,
                              void* d_out, int out_size)
{
    const float* x  = (const float*)d_in[0];   // (8,112,64,64)
    const float* pw = (const float*)d_in[1];   // (378,112,3,3)
    const float* pb = (const float*)d_in[2];   // (378,)
    const float* w  = (const float*)d_in[3];   // (112,112,3,3)
    const float* bs = (const float*)d_in[4];   // (112,)
    float* out = (float*)d_out;                // (8,112,64,64)

    dim3 g1(6, 32, 8);
    k1_pgconv<<<g1, 256>>>(x, pw, pb);

    const int tot2 = BB * GG * K2 * HW;
    k2_sample<<<(tot2 + 255) / 256, 256>>>(x);

    dim3 g3(32, 8);
    k3_gemm<<<g3, 256>>>(w, bs, out);
}

// round 17
// speedup vs baseline: 1.7428x; 1.7428x over previous
#include <cuda_runtime.h>
#include <cstdint>
#include <math.h>

// ---------------------------------------------------------------------------
// DeformableConv2d: B=8, C=112, H=W=64, O=112, K=3, G=14, stride=1, pad=1
// pg channels: 378 = 252 offsets (interleaved dy/dx per (g,k)) + 126 mask
// ---------------------------------------------------------------------------

#define BB 8
#define CC 112
#define HH 64
#define WW 64
#define OO 112
#define GG 14
#define K2 9
#define PGC 378            // 3*G*K2
#define HW 4096            // 64*64
#define CK 1008            // C*K2

// scratch (allocation-free rule: static __device__ arrays)
__device__ float g_pg[BB * PGC * HW];          // 47.25 MiB
__device__ float g_smp[BB * CC * K2 * HW];     // 126 MiB

// ---- tf32 convert (round-to-nearest) --------------------------------------
__device__ __forceinline__ unsigned tf32_of(float f)
{
    unsigned r;
    asm("cvt.rna.tf32.f32 %0, %1;" : "=r"(r) : "f"(f));
    return r;
}

// ---------------------------------------------------------------------------
// Kernel 1 (tf32 tensor-core): pg = conv3x3(x, pg_weight, pad=1) + pg_bias
// Block 256 thr (8 warps) -> M=64 oc x N=256 px (4 output rows x 64 cols).
// K = 112 ch x 9 taps, chunked 8 ch at a time; per chunk 9 mma-K steps (taps).
// Warp layout: r = wid>>1 (output row 0..3), col0w = (wid&1)*32.
// Per warp: 4 mtiles (16 oc) x 4 ntiles (8 px). mma.m16n8k8 tf32, fp32 accum.
// smem strides 72 make both A and B fragment loads bank-conflict-free.
// ---------------------------------------------------------------------------
__global__ __launch_bounds__(256) void k1_pgconv(const float* __restrict__ x,
                                                 const float* __restrict__ pw,
                                                 const float* __restrict__ pb)
{
    const int ocTile = blockIdx.x;     // 0..5  (6*64 = 384 >= 378)
    const int rq     = blockIdx.y;     // 0..15 row quad
    const int b      = blockIdx.z;     // 0..7
    const int t      = threadIdx.x;
    const int oh0    = rq * 4;

    const int wid  = t >> 5;
    const int lane = t & 31;
    const int gid  = lane >> 2;        // 0..7
    const int tig  = lane & 3;         // 0..3
    const int r      = wid >> 1;       // output row within quad
    const int col0w  = (wid & 1) * 32; // warp column half
    const int oc0    = ocTile * 64;

    // xs: input rows oh0-1 .. oh0+4 (6), 8 ch, cols 0..65 (halo 0,65), stride 72
    __shared__ unsigned xs[6 * 8 * 72];     // 13.8 KB
    // ws: 72 ck (cl*9+tap) x 64 oc, stride 72
    __shared__ unsigned ws[72 * 72];        // 20.7 KB

    // halo columns always OOB (pad=1) -> zero once
    if (t < 96) {
        int row = t >> 4, ch = (t >> 1) & 7, side = t & 1;
        xs[row * 576 + ch * 72 + side * 65] = 0u;
    }

    float d[4][4][4];
#pragma unroll
    for (int mt = 0; mt < 4; ++mt)
#pragma unroll
        for (int nt = 0; nt < 4; ++nt)
#pragma unroll
            for (int i = 0; i < 4; ++i) d[mt][nt][i] = 0.f;

    for (int c0 = 0; c0 < CC; c0 += 8) {
        __syncthreads();
        // ---- x fill: 6 rows x 8 ch x 64 cols (3072 = 12*256), cvt to tf32
        {
            int idx = t;
#pragma unroll
            for (int i = 0; i < 12; ++i, idx += 256) {
                int col = idx & 63;
                int ch  = (idx >> 6) & 7;
                int row = idx >> 9;
                int ih  = oh0 - 1 + row;
                float v = 0.f;
                if ((unsigned)ih < 64u)
                    v = x[(((size_t)b * CC + c0 + ch) * HH + ih) * WW + col];
                xs[row * 576 + ch * 72 + col + 1] = tf32_of(v);
            }
        }
        // ---- w fill: 72 ck x 64 oc (4608 = 18*256), cvt to tf32
        {
            int idx = t;
#pragma unroll
            for (int i = 0; i < 18; ++i, idx += 256) {
                int ocl = idx & 63;
                int ck  = idx >> 6;
                int oc  = oc0 + ocl;
                float v = (oc < PGC) ? pw[(size_t)oc * CK + c0 * 9 + ck] : 0.f;
                ws[ck * 72 + ocl] = tf32_of(v);
            }
        }
        __syncthreads();

#pragma unroll
        for (int ky = 0; ky < 3; ++ky) {
#pragma unroll
            for (int kx = 0; kx < 3; ++kx) {
                const int tap = ky * 3 + kx;
                // A fragments: ws[(cl*9+tap)*72 + oc]; cl = tig / tig+4
                unsigned a[4][4];
#pragma unroll
                for (int mt = 0; mt < 4; ++mt) {
                    const unsigned* wr0 = &ws[(tig * 9 + tap) * 72 + mt * 16 + gid];
                    const unsigned* wr1 = &ws[((tig + 4) * 9 + tap) * 72 + mt * 16 + gid];
                    a[mt][0] = wr0[0];
                    a[mt][1] = wr0[8];
                    a[mt][2] = wr1[0];
                    a[mt][3] = wr1[8];
                }
                const unsigned* xrow = &xs[(r + ky) * 576 + kx];
#pragma unroll
                for (int nt = 0; nt < 4; ++nt) {
                    int colOut = col0w + nt * 8 + gid;
                    unsigned b0 = xrow[tig * 72 + colOut];
                    unsigned b1 = xrow[(tig + 4) * 72 + colOut];
#pragma unroll
                    for (int mt = 0; mt < 4; ++mt) {
                        asm volatile(
                            "mma.sync.aligned.m16n8k8.row.col.f32.tf32.tf32.f32 "
                            "{%0,%1,%2,%3}, {%4,%5,%6,%7}, {%8,%9}, {%0,%1,%2,%3};"
                            : "+f"(d[mt][nt][0]), "+f"(d[mt][nt][1]),
                              "+f"(d[mt][nt][2]), "+f"(d[mt][nt][3])
                            : "r"(a[mt][0]), "r"(a[mt][1]),
                              "r"(a[mt][2]), "r"(a[mt][3]),
                              "r"(b0), "r"(b1));
                    }
                }
            }
        }
    }

    // epilogue: D(row=gid/+8, col=2*tig/+1) -> g_pg + bias
#pragma unroll
    for (int mt = 0; mt < 4; ++mt) {
        int ocA = oc0 + mt * 16 + gid;      // rows gid
        int ocB = ocA + 8;                  // rows gid+8
        float bvA = (ocA < PGC) ? pb[ocA] : 0.f;
        float bvB = (ocB < PGC) ? pb[ocB] : 0.f;
#pragma unroll
        for (int nt = 0; nt < 4; ++nt) {
            int col = col0w + nt * 8 + 2 * tig;
            if (ocA < PGC) {
                float* dst = &g_pg[(((size_t)b * PGC + ocA) * HH + oh0 + r) * WW + col];
                *(float2*)dst = make_float2(d[mt][nt][0] + bvA, d[mt][nt][1] + bvA);
            }
            if (ocB < PGC) {
                float* dst = &g_pg[(((size_t)b * PGC + ocB) * HH + oh0 + r) * WW + col];
                *(float2*)dst = make_float2(d[mt][nt][2] + bvB, d[mt][nt][3] + bvB);
            }
        }
    }
}

// ---------------------------------------------------------------------------
// Kernel 2: bilinear sampling * sigmoid(mask)
// One thread per (b, g, k, pixel). dy = pg[g*18+2k], dx = pg[g*18+2k+1]
// (interleaved!), mask = sigmoid(pg[252 + g*9 + k]).
// Output layout: g_smp[b][c][k][p]
// ---------------------------------------------------------------------------
__global__ __launch_bounds__(256) void k2_sample(const float* __restrict__ x)
{
    int gid = blockIdx.x * 256 + threadIdx.x;
    const int TOT = BB * GG * K2 * HW;   // 4,128,768
    if (gid >= TOT) return;

    int p    = gid & (HW - 1);
    int rest = gid >> 12;
    int gk   = rest % (GG * K2);
    int b    = rest / (GG * K2);
    int g    = gk / 9;
    int k    = gk - g * 9;
    int oh   = p >> 6, ow = p & 63;

    const float* pgb = g_pg + (size_t)b * PGC * HW;
    float dy = pgb[(g * 18 + 2 * k) * HW + p];
    float dx = pgb[(g * 18 + 2 * k + 1) * HW + p];
    float m  = pgb[(252 + gk) * HW + p];
    float mask = 1.f / (1.f + expf(-m));

    float yy = (float)(oh - 1 + k / 3) + dy;
    float xx = (float)(ow - 1 + k % 3) + dx;
    float y0f = floorf(yy), x0f = floorf(xx);
    float wy1 = yy - y0f, wx1 = xx - x0f;
    float wy0 = 1.f - wy1, wx0 = 1.f - wx1;
    int y0 = (int)y0f, x0i = (int)x0f;
    int y1 = y0 + 1, x1 = x0i + 1;
    bool vy0 = (unsigned)y0 < 64u, vy1 = (unsigned)y1 < 64u;
    bool vx0 = (unsigned)x0i < 64u, vx1 = (unsigned)x1 < 64u;

    float w00 = (vy0 && vx0) ? wy0 * wx0 * mask : 0.f;
    float w01 = (vy0 && vx1) ? wy0 * wx1 * mask : 0.f;
    float w10 = (vy1 && vx0) ? wy1 * wx0 * mask : 0.f;
    float w11 = (vy1 && vx1) ? wy1 * wx1 * mask : 0.f;

    int yc0 = min(max(y0, 0), 63), yc1 = min(max(y1, 0), 63);
    int xc0 = min(max(x0i, 0), 63), xc1 = min(max(x1, 0), 63);
    int i00 = yc0 * 64 + xc0, i01 = yc0 * 64 + xc1;
    int i10 = yc1 * 64 + xc0, i11 = yc1 * 64 + xc1;

    const float* xb = x + ((size_t)b * CC + g * 8) * HW;
    float* out = g_smp + ((((size_t)b * CC + g * 8) * K2) + k) * HW + p;
#pragma unroll
    for (int c = 0; c < 8; ++c) {
        const float* xc = xb + (size_t)c * HW;
        float v = w00 * xc[i00] + w01 * xc[i01] + w10 * xc[i10] + w11 * xc[i11];
        out[(size_t)c * K2 * HW] = v;
    }
}

// ---------------------------------------------------------------------------
// Kernel 3: out[b,o,p] = bias[o] + sum_ck smp[b,ck,p] * W[o,ck]
// Block: 256 threads -> 112 O x 128 px. Thread tile: 7 oc x 8 px. K-chunk 16.
// ---------------------------------------------------------------------------
__global__ __launch_bounds__(256) void k3_gemm(const float* __restrict__ w2,
                                               const float* __restrict__ bias,
                                               float* __restrict__ out)
{
    const int pt = blockIdx.x;       // 0..31
    const int b  = blockIdx.y;       // 0..7
    const int t  = threadIdx.x;
    const int pxg = t & 15;          // 16 groups * 8 px
    const int ocg = t >> 4;          // 16 groups * 7 oc
    const int p0  = pt * 128;
    const int px0 = pxg * 8;

    __shared__ __align__(16) float ss[16 * 128];   // [ckl][px]
    __shared__ float ws2[16 * 113];                // [ckl][o] pad

    float acc[7][8];
#pragma unroll
    for (int j = 0; j < 7; ++j)
#pragma unroll
        for (int i = 0; i < 8; ++i) acc[j][i] = 0.f;

    const float* sb = g_smp + (size_t)b * CK * HW + p0;

    for (int ck0 = 0; ck0 < CK; ck0 += 16) {
        __syncthreads();
        {
            int idx = t;
#pragma unroll
            for (int i = 0; i < 8; ++i, idx += 256) {
                int pxl = idx & 127;
                int ckl = idx >> 7;
                ss[ckl * 128 + pxl] = sb[(size_t)(ck0 + ckl) * HW + pxl];
            }
        }
        {
            int idx = t;
#pragma unroll
            for (int i = 0; i < 7; ++i, idx += 256) {
                int ckl = idx & 15;
                int o   = idx >> 4;
                ws2[ckl * 113 + o] = w2[(size_t)o * CK + ck0 + ckl];
            }
        }
        __syncthreads();

#pragma unroll
        for (int ckl = 0; ckl < 16; ++ckl) {
            float4 sa = *(const float4*)(&ss[ckl * 128 + px0]);
            float4 sc = *(const float4*)(&ss[ckl * 128 + px0 + 4]);
            const float* wr = &ws2[ckl * 113 + ocg * 7];
#pragma unroll
            for (int j = 0; j < 7; ++j) {
                float wv = wr[j];
                acc[j][0] = fmaf(wv, sa.x, acc[j][0]);
                acc[j][1] = fmaf(wv, sa.y, acc[j][1]);
                acc[j][2] = fmaf(wv, sa.z, acc[j][2]);
                acc[j][3] = fmaf(wv, sa.w, acc[j][3]);
                acc[j][4] = fmaf(wv, sc.x, acc[j][4]);
                acc[j][5] = fmaf(wv, sc.y, acc[j][5]);
                acc[j][6] = fmaf(wv, sc.z, acc[j][6]);
                acc[j][7] = fmaf(wv, sc.w, acc[j][7]);
            }
        }
    }

#pragma unroll
    for (int j = 0; j < 7; ++j) {
        int o = ocg * 7 + j;
        float bv = bias[o];
        float* dst = &out[(((size_t)b * OO + o) * HW) + p0 + px0];
        float4 v0 = make_float4(acc[j][0] + bv, acc[j][1] + bv,
                                acc[j][2] + bv, acc[j][3] + bv);
        float4 v1 = make_float4(acc[j][4] + bv, acc[j][5] + bv,
                                acc[j][6] + bv, acc[j][7] + bv);
        *(float4*)(dst)     = v0;
        *(float4*)(dst + 4) = v1;
    }
}

// ---------------------------------------------------------------------------
extern "C" void kernel_launch(void* const* d_in, const int* in_sizes, int n_in,
                              void* d_out, int out_size)
{
    const float* x  = (const float*)d_in[0];   // (8,112,64,64)
    const float* pw = (const float*)d_in[1];   // (378,112,3,3)
    const float* pb = (const float*)d_in[2];   // (378,)
    const float* w  = (const float*)d_in[3];   // (112,112,3,3)
    const float* bs = (const float*)d_in[4];   // (112,)
    float* out = (float*)d_out;                // (8,112,64,64)

    dim3 g1(6, 16, 8);
    k1_pgconv<<<g1, 256>>>(x, pw, pb);

    const int tot2 = BB * GG * K2 * HW;
    k2_sample<<<(tot2 + 255) / 256, 256>>>(x);

    dim3 g3(32, 8);
    k3_gemm<<<g3, 256>>>(w, bs, out);
}